// round 1
// baseline (speedup 1.0000x reference)
#include <cuda_runtime.h>

// Fused elementwise: out = (x+2) + 3x - (x-1)*(0.5x) = -0.5x^2 + 4.5x + 2
// 8192*16384 = 134,217,728 fp32 elements. Pure HBM-streaming kernel.

__device__ __forceinline__ float fuse(float x) {
    // -0.5*x*x + 4.5*x + 2  via two FMAs: t = fma(-0.5f, x, 4.5f); r = fma(t, x, 2.0f)
    float t = fmaf(-0.5f, x, 4.5f);
    return fmaf(t, x, 2.0f);
}

__global__ void fused_elemwise_v4(const float4* __restrict__ in,
                                  float4* __restrict__ out,
                                  int n4) {
    int i = blockIdx.x * blockDim.x + threadIdx.x;
    if (i < n4) {
        float4 v = in[i];
        float4 r;
        r.x = fuse(v.x);
        r.y = fuse(v.y);
        r.z = fuse(v.z);
        r.w = fuse(v.w);
        out[i] = r;
    }
}

// Tail handler for non-multiple-of-4 (not needed here, but safe).
__global__ void fused_elemwise_tail(const float* __restrict__ in,
                                    float* __restrict__ out,
                                    int start, int n) {
    int i = start + blockIdx.x * blockDim.x + threadIdx.x;
    if (i < n) out[i] = fuse(in[i]);
}

extern "C" void kernel_launch(void* const* d_in, const int* in_sizes, int n_in,
                              void* d_out, int out_size) {
    const float* x = (const float*)d_in[0];
    float* out = (float*)d_out;
    int n = in_sizes[0];

    int n4 = n / 4;
    if (n4 > 0) {
        int threads = 256;
        int blocks = (n4 + threads - 1) / threads;
        fused_elemwise_v4<<<blocks, threads>>>((const float4*)x, (float4*)out, n4);
    }
    int rem = n - n4 * 4;
    if (rem > 0) {
        fused_elemwise_tail<<<1, 256>>>(x, out, n4 * 4, n);
    }
}

// round 5
// speedup vs baseline: 1.0798x; 1.0798x over previous
#include <cuda_runtime.h>

// Fused elementwise: out = (x+2) + 3x - (x-1)*(0.5x) = -0.5x^2 + 4.5x + 2
// 134,217,728 fp32 elements. Pure HBM-streaming kernel.
// R1: 4x batched LDG.128 per thread (MLP=4) + streaming cache hints (__ldcs/__stcs).

__device__ __forceinline__ float fuse(float x) {
    float t = fmaf(-0.5f, x, 4.5f);
    return fmaf(t, x, 2.0f);
}

__device__ __forceinline__ float4 fuse4(float4 v) {
    float4 r;
    r.x = fuse(v.x);
    r.y = fuse(v.y);
    r.z = fuse(v.z);
    r.w = fuse(v.w);
    return r;
}

template <int BATCH>
__global__ void fused_elemwise_v4b(const float4* __restrict__ in,
                                   float4* __restrict__ out,
                                   int n4) {
    const int stride = gridDim.x * blockDim.x;
    const int base = blockIdx.x * blockDim.x + threadIdx.x;

    // Fast path: all BATCH indices in range (true for every block when the
    // grid exactly covers n4).
    if (base + (BATCH - 1) * stride < n4) {
        float4 v[BATCH];
#pragma unroll
        for (int k = 0; k < BATCH; k++)
            v[k] = __ldcs(&in[base + k * stride]);
#pragma unroll
        for (int k = 0; k < BATCH; k++)
            __stcs(&out[base + k * stride], fuse4(v[k]));
    } else {
#pragma unroll
        for (int k = 0; k < BATCH; k++) {
            int i = base + k * stride;
            if (i < n4) __stcs(&out[i], fuse4(__ldcs(&in[i])));
        }
    }
}

__global__ void fused_elemwise_tail(const float* __restrict__ in,
                                    float* __restrict__ out,
                                    int start, int n) {
    int i = start + blockIdx.x * blockDim.x + threadIdx.x;
    if (i < n) out[i] = fuse(in[i]);
}

extern "C" void kernel_launch(void* const* d_in, const int* in_sizes, int n_in,
                              void* d_out, int out_size) {
    const float* x = (const float*)d_in[0];
    float* out = (float*)d_out;
    int n = in_sizes[0];

    constexpr int BATCH = 4;
    constexpr int THREADS = 256;

    int n4 = n / 4;
    if (n4 > 0) {
        int threads_needed = (n4 + BATCH - 1) / BATCH;
        int blocks = (threads_needed + THREADS - 1) / THREADS;
        fused_elemwise_v4b<BATCH><<<blocks, THREADS>>>(
            (const float4*)x, (float4*)out, n4);
    }
    int rem = n - n4 * 4;
    if (rem > 0) {
        fused_elemwise_tail<<<1, 256>>>(x, out, n4 * 4, n);
    }
}